// round 8
// baseline (speedup 1.0000x reference)
#include <cuda_runtime.h>
#include <cuda_bf16.h>
#include <math.h>
#include <stdint.h>

#define N_TOKENS 16384
#define HIDDEN   4096
#define NEXP     64
#define TOPK     8

#define BM       128          // tokens per CTA
#define TK       64           // k per tile
#define NKT      (HIDDEN/TK)  // 64 k-tiles
#define NTH      256          // 8 warps: 4 (M) x 2 (N), warp tile 32x32

#define A_TERM_BYTES (BM*TK*2)        // 16384
#define B_TERM_BYTES (NEXP*TK*2)      // 8192
#define A_STAGE      (3*A_TERM_BYTES) // 49152
#define B_STAGE      (3*B_TERM_BYTES) // 24576
#define STAGE_BYTES  (A_STAGE+B_STAGE)// 73728
#define SMEM_BYTES   (1024 + 2*STAGE_BYTES)
#define CRS          72               // C smem row stride (floats)

// pre-split, pre-swizzled W: [tile t][term s][expert row][64 k] bf16
__device__ __align__(16) unsigned char g_wb[NKT * B_STAGE];

// ---------------- helpers ----------------
__device__ __forceinline__ uint32_t smem_u32(const void* p) {
    uint32_t a;
    asm("{ .reg .u64 t; cvta.to.shared.u64 t, %1; cvt.u32.u64 %0, t; }" : "=r"(a) : "l"(p));
    return a;
}
__device__ __forceinline__ uint32_t sw128(uint32_t o) { return o ^ ((o >> 3) & 0x70); }

#define PACK_BF16X2(res, lo, hi) \
    asm("cvt.rn.satfinite.bf16x2.f32 %0, %1, %2;" : "=r"(res) : "f"(hi), "f"(lo))

__device__ __forceinline__ void sts64(uint32_t a, uint32_t x, uint32_t y) {
    asm volatile("st.shared.v2.b32 [%0], {%1,%2};" :: "r"(a), "r"(x), "r"(y) : "memory");
}
__device__ __forceinline__ void cp_async16(uint32_t dst, const void* src) {
    asm volatile("cp.async.cg.shared.global [%0], [%1], 16;" :: "r"(dst), "l"(src) : "memory");
}
#define CP_COMMIT() asm volatile("cp.async.commit_group;" ::: "memory")
#define CP_WAIT0()  asm volatile("cp.async.wait_group 0;" ::: "memory")

__device__ __forceinline__ void ldsm_x4(uint32_t r[4], uint32_t addr) {
    asm volatile("ldmatrix.sync.aligned.m8n8.x4.shared.b16 {%0,%1,%2,%3}, [%4];"
        : "=r"(r[0]), "=r"(r[1]), "=r"(r[2]), "=r"(r[3]) : "r"(addr));
}
__device__ __forceinline__ void mma16816(float c[4], const uint32_t a[4],
                                         uint32_t b0, uint32_t b1) {
    asm volatile("mma.sync.aligned.m16n8k16.row.col.f32.bf16.bf16.f32 "
        "{%0,%1,%2,%3}, {%4,%5,%6,%7}, {%8,%9}, {%0,%1,%2,%3};"
        : "+f"(c[0]), "+f"(c[1]), "+f"(c[2]), "+f"(c[3])
        : "r"(a[0]), "r"(a[1]), "r"(a[2]), "r"(a[3]), "r"(b0), "r"(b1));
}
// one A m16 fragment against one B n16 fragment (two n8 MMAs)
__device__ __forceinline__ void mma_n16(float c0[4], float c1[4],
                                        const uint32_t a[4], const uint32_t Bf[4]) {
    mma16816(c0, a, Bf[0], Bf[2]);
    mma16816(c1, a, Bf[1], Bf[3]);
}

__device__ __forceinline__ void split2(float v, float& f0, float& f1, float& r2) {
    f0 = __bfloat162float(__float2bfloat16_rn(v));
    float r1 = v - f0;                              // exact (Sterbenz)
    f1 = __bfloat162float(__float2bfloat16_rn(r1));
    r2 = r1 - f1;                                   // exact; rounded to bf16 at pack
}

// ---------------- W pre-split kernel ----------------
__global__ void wsplit_kernel(const float* __restrict__ W) {
    const int t = blockIdx.x;                 // k-tile
    unsigned char* dst = g_wb + (size_t)t * B_STAGE;
    for (int item = threadIdx.x; item < NEXP * 16; item += blockDim.x) {
        const int e  = item >> 4;             // expert row
        const int kq = (item & 15) * 4;       // k within tile
        float4 w = *(const float4*)(W + (size_t)e * HIDDEN + t * TK + kq);
        float v[4] = {w.x, w.y, w.z, w.w};
        float f0[4], f1[4], f2[4];
#pragma unroll
        for (int i = 0; i < 4; i++) split2(v[i], f0[i], f1[i], f2[i]);
        uint32_t u0a, u0b, u1a, u1b, u2a, u2b;
        PACK_BF16X2(u0a, f0[0], f0[1]); PACK_BF16X2(u0b, f0[2], f0[3]);
        PACK_BF16X2(u1a, f1[0], f1[1]); PACK_BF16X2(u1b, f1[2], f1[3]);
        PACK_BF16X2(u2a, f2[0], f2[1]); PACK_BF16X2(u2b, f2[2], f2[3]);
        const uint32_t off = sw128((uint32_t)(e * 128 + kq * 2));
        *(uint2*)(dst + 0 * B_TERM_BYTES + off) = make_uint2(u0a, u0b);
        *(uint2*)(dst + 1 * B_TERM_BYTES + off) = make_uint2(u1a, u1b);
        *(uint2*)(dst + 2 * B_TERM_BYTES + off) = make_uint2(u2a, u2b);
    }
}

// MMA over one smem stage, warp tile 32x32.
// accX[im][n8][4], im in {0,1} (m16), n8 in {0..3}.
// Main product (a0,b0) -> accM (drained per tile); other 5 -> accC.
__device__ __forceinline__ void mma_stage(
    uint32_t Ab, uint32_t Bb, float accM[2][4][4], float accC[2][4][4],
    uint32_t arow0, uint32_t arow1, uint32_t brow0, uint32_t brow1,
    uint32_t colb, uint32_t swz)
{
#pragma unroll
    for (int k16 = 0; k16 < 4; k16++) {
        const uint32_t coff = (colb + 32u * k16) ^ swz;
        uint32_t Bf[3][2][4];   // [term][n16 tile][regs]
#pragma unroll
        for (int tb = 0; tb < 3; tb++) {
            ldsm_x4(Bf[tb][0], Bb + tb * B_TERM_BYTES + brow0 + coff);
            ldsm_x4(Bf[tb][1], Bb + tb * B_TERM_BYTES + brow1 + coff);
        }
        // ta = 0: (0,0) -> accM, (0,1),(0,2) -> accC
        {
            uint32_t Af0[4], Af1[4];
            ldsm_x4(Af0, Ab + 0 * A_TERM_BYTES + arow0 + coff);
            ldsm_x4(Af1, Ab + 0 * A_TERM_BYTES + arow1 + coff);
            mma_n16(accM[0][0], accM[0][1], Af0, Bf[0][0]);
            mma_n16(accM[0][2], accM[0][3], Af0, Bf[0][1]);
            mma_n16(accM[1][0], accM[1][1], Af1, Bf[0][0]);
            mma_n16(accM[1][2], accM[1][3], Af1, Bf[0][1]);
#pragma unroll
            for (int tb = 1; tb < 3; tb++) {
                mma_n16(accC[0][0], accC[0][1], Af0, Bf[tb][0]);
                mma_n16(accC[0][2], accC[0][3], Af0, Bf[tb][1]);
                mma_n16(accC[1][0], accC[1][1], Af1, Bf[tb][0]);
                mma_n16(accC[1][2], accC[1][3], Af1, Bf[tb][1]);
            }
        }
        // ta = 1: (1,0),(1,1) -> accC
        {
            uint32_t Af0[4], Af1[4];
            ldsm_x4(Af0, Ab + 1 * A_TERM_BYTES + arow0 + coff);
            ldsm_x4(Af1, Ab + 1 * A_TERM_BYTES + arow1 + coff);
#pragma unroll
            for (int tb = 0; tb < 2; tb++) {
                mma_n16(accC[0][0], accC[0][1], Af0, Bf[tb][0]);
                mma_n16(accC[0][2], accC[0][3], Af0, Bf[tb][1]);
                mma_n16(accC[1][0], accC[1][1], Af1, Bf[tb][0]);
                mma_n16(accC[1][2], accC[1][3], Af1, Bf[tb][1]);
            }
        }
        // ta = 2: (2,0) -> accC
        {
            uint32_t Af0[4], Af1[4];
            ldsm_x4(Af0, Ab + 2 * A_TERM_BYTES + arow0 + coff);
            ldsm_x4(Af1, Ab + 2 * A_TERM_BYTES + arow1 + coff);
            mma_n16(accC[0][0], accC[0][1], Af0, Bf[0][0]);
            mma_n16(accC[0][2], accC[0][3], Af0, Bf[0][1]);
            mma_n16(accC[1][0], accC[1][1], Af1, Bf[0][0]);
            mma_n16(accC[1][2], accC[1][3], Af1, Bf[0][1]);
        }
    }
}

#define DRAIN_M()                                              \
    do {                                                       \
        _Pragma("unroll")                                      \
        for (int _i = 0; _i < 2; _i++)                         \
        _Pragma("unroll")                                      \
        for (int _j = 0; _j < 4; _j++)                         \
        _Pragma("unroll")                                      \
        for (int _q = 0; _q < 4; _q++) {                       \
            sum[_i][_j][_q] += accM[_i][_j][_q];               \
            accM[_i][_j][_q] = 0.0f;                           \
        }                                                      \
    } while (0)

// ---------------- main kernel ----------------
__global__ __launch_bounds__(NTH, 1) void router_kernel(
    const float* __restrict__ x,
    const float* __restrict__ b,
    float* __restrict__ out)
{
    extern __shared__ __align__(16) char dsmem[];
    float* biasS = (float*)dsmem;                 // [64]
    float* Cs    = (float*)(dsmem + 1024);        // epilogue: [128][CRS] (stage-0 area)
    const uint32_t TBu = smem_u32(dsmem + 1024);  // stage 0 base (smem u32)

    const int tid = threadIdx.x;
    const int wid = tid >> 5;
    const int lid = tid & 31;
    const int block_m = blockIdx.x * BM;

    // warp grid: 4 (M) x 2 (N), warp tile 32x32
    const int wm = (wid & 3) * 32;
    const int wn = (wid >> 2) * 32;

    // ldmatrix lane addressing (pre-swizzle components)
    const uint32_t lrow = (lid & 7) + ((lid >> 3) & 1) * 8;  // 0..15
    const uint32_t swz  = (lrow & 7) << 4;
    const uint32_t colb = (lid >> 4) * 16;
    const uint32_t arow0 = (wm + lrow) * 128;
    const uint32_t arow1 = arow0 + 16 * 128;
    const uint32_t brow0 = (wn + lrow) * 128;
    const uint32_t brow1 = brow0 + 16 * 128;

    // ---- global load mapping for A conversion: 32 floats/thread
    const int r  = tid >> 1;          // token row 0..127
    const int kq = (tid & 1) * 32;    // k base within tile
    const float* xrow = x + (size_t)(block_m + r) * HIDDEN + kq;

    float accM[2][4][4], accC[2][4][4], sum[2][4][4];
#pragma unroll
    for (int i = 0; i < 2; i++)
#pragma unroll
        for (int j = 0; j < 4; j++)
#pragma unroll
            for (int q = 0; q < 4; q++) {
                accM[i][j][q] = 0.0f; accC[i][j][q] = 0.0f; sum[i][j][q] = 0.0f;
            }

    const uint32_t stage[2] = {TBu, TBu + STAGE_BYTES};

    // cp.async B(0) into stage 0
#pragma unroll
    for (int j = 0; j < 6; j++) {
        const int idx = tid + j * NTH;
        cp_async16(stage[0] + A_STAGE + idx * 16, g_wb + (size_t)idx * 16);
    }
    CP_COMMIT();

    // prefetch A(0) regs
    float4 ax[8];
#pragma unroll
    for (int j = 0; j < 8; j++) ax[j] = *(const float4*)(xrow + j * 4);

    if (tid < NEXP) biasS[tid] = b[tid];

    for (int t = 0; t < NKT; ++t) {
        const int p = t & 1;
        const uint32_t Abase = stage[p];

        // convert + store A(t) (3 bf16 terms, SW128)
#pragma unroll
        for (int j = 0; j < 8; j++) {
            float v[4] = {ax[j].x, ax[j].y, ax[j].z, ax[j].w};
            float f0[4], f1[4], f2[4];
#pragma unroll
            for (int i = 0; i < 4; i++) split2(v[i], f0[i], f1[i], f2[i]);
            uint32_t u0a, u0b, u1a, u1b, u2a, u2b;
            PACK_BF16X2(u0a, f0[0], f0[1]); PACK_BF16X2(u0b, f0[2], f0[3]);
            PACK_BF16X2(u1a, f1[0], f1[1]); PACK_BF16X2(u1b, f1[2], f1[3]);
            PACK_BF16X2(u2a, f2[0], f2[1]); PACK_BF16X2(u2b, f2[2], f2[3]);
            const uint32_t off = sw128((uint32_t)(r * 128 + (kq + j * 4) * 2));
            sts64(Abase + 0 * A_TERM_BYTES + off, u0a, u0b);
            sts64(Abase + 1 * A_TERM_BYTES + off, u1a, u1b);
            sts64(Abase + 2 * A_TERM_BYTES + off, u2a, u2b);
        }

        // prefetch A(t+1)
        if (t + 1 < NKT) {
            const float* xn = xrow + (size_t)(t + 1) * TK;
#pragma unroll
            for (int j = 0; j < 8; j++) ax[j] = *(const float4*)(xn + j * 4);
        }

        // MMA over the PREVIOUS stage (tile t-1), then drain main acc
        if (t > 0) {
            mma_stage(stage[p ^ 1], stage[p ^ 1] + A_STAGE,
                      accM, accC, arow0, arow1, brow0, brow1, colb, swz);
            DRAIN_M();
        }

        CP_WAIT0();          // B(t) landed (issued an iteration ago)
        __syncthreads();     // stage p fully built; stage p^1 reads finished

        // cp.async B(t+1) into stage p^1 (its tile-(t-1) data is dead now)
        if (t + 1 < NKT) {
            const unsigned char* src = g_wb + (size_t)(t + 1) * B_STAGE;
#pragma unroll
            for (int j = 0; j < 6; j++) {
                const int idx = tid + j * NTH;
                cp_async16(stage[p ^ 1] + A_STAGE + idx * 16, src + (size_t)idx * 16);
            }
            CP_COMMIT();
        }
    }
    // final stage (tile 63 sits in stage 1)
    mma_stage(stage[1], stage[1] + A_STAGE,
              accM, accC, arow0, arow1, brow0, brow1, colb, swz);
    DRAIN_M();

    // ---- dump C = sum + corrections to smem (stage-0 area is dead)
#pragma unroll
    for (int im = 0; im < 2; im++)
#pragma unroll
        for (int n8 = 0; n8 < 4; n8++) {
            const int r0 = wm + im * 16 + (lid >> 2);
            const int c0 = wn + n8 * 8 + (lid & 3) * 2;
            *(float2*)&Cs[r0 * CRS + c0] =
                make_float2(sum[im][n8][0] + accC[im][n8][0],
                            sum[im][n8][1] + accC[im][n8][1]);
            *(float2*)&Cs[(r0 + 8) * CRS + c0] =
                make_float2(sum[im][n8][2] + accC[im][n8][2],
                            sum[im][n8][3] + accC[im][n8][3]);
        }
    __syncthreads();

    if (tid < BM) {
        const int m  = tid;
        const int gm = block_m + m;
        float v[NEXP];
#pragma unroll
        for (int e = 0; e < NEXP; e++) v[e] = Cs[m * CRS + e] + biasS[e];

        float* outR    = out;
        float* outWt   = out + (size_t)N_TOKENS * NEXP;
        float* outIdx  = outWt + (size_t)N_TOKENS * TOPK;
        float* outMask = outIdx + (size_t)N_TOKENS * TOPK;

        float* dst = outR + (size_t)gm * NEXP;
#pragma unroll
        for (int e = 0; e < NEXP; e += 4)
            *(float4*)(dst + e) = make_float4(v[e], v[e + 1], v[e + 2], v[e + 3]);

        // top-8, strict > (first index on ties, matching jax top_k)
        unsigned long long used = 0ull;
        float vals[TOPK]; int idxs[TOPK];
#pragma unroll
        for (int k = 0; k < TOPK; k++) {
            float best = -INFINITY; int bi = 0;
#pragma unroll
            for (int e = 0; e < NEXP; e++) {
                const bool free_e = !((used >> e) & 1ull);
                if (free_e && v[e] > best) { best = v[e]; bi = e; }
            }
            used |= 1ull << bi;
            vals[k] = best; idxs[k] = bi;
        }
        const float mx = vals[0];
        float ex[TOPK], s = 0.0f;
#pragma unroll
        for (int k = 0; k < TOPK; k++) { ex[k] = expf(vals[k] - mx); s += ex[k]; }
        const float inv = 1.0f / s;

        *(float4*)(outWt + (size_t)gm * TOPK) =
            make_float4(ex[0] * inv, ex[1] * inv, ex[2] * inv, ex[3] * inv);
        *(float4*)(outWt + (size_t)gm * TOPK + 4) =
            make_float4(ex[4] * inv, ex[5] * inv, ex[6] * inv, ex[7] * inv);
        *(float4*)(outIdx + (size_t)gm * TOPK) =
            make_float4((float)idxs[0], (float)idxs[1], (float)idxs[2], (float)idxs[3]);
        *(float4*)(outIdx + (size_t)gm * TOPK + 4) =
            make_float4((float)idxs[4], (float)idxs[5], (float)idxs[6], (float)idxs[7]);
#pragma unroll
        for (int k = 0; k < TOPK; k++)
            outMask[(size_t)(idxs[k] * TOPK + k) * N_TOKENS + gm] = 1.0f;
    }
}

extern "C" void kernel_launch(void* const* d_in, const int* in_sizes, int n_in,
                              void* d_out, int out_size)
{
    const float* x = (const float*)d_in[0];
    const float* W = (const float*)d_in[1];
    const float* b = (const float*)d_in[2];
    float* out = (float*)d_out;

    // zero the expert_mask region (rest of out fully overwritten)
    float* mask = out + (size_t)N_TOKENS * NEXP + 2 * (size_t)N_TOKENS * TOPK;
    cudaMemsetAsync(mask, 0, (size_t)NEXP * TOPK * N_TOKENS * sizeof(float), 0);

    wsplit_kernel<<<NKT, 256>>>(W);

    cudaFuncSetAttribute(router_kernel,
                         cudaFuncAttributeMaxDynamicSharedMemorySize, SMEM_BYTES);
    router_kernel<<<N_TOKENS / BM, NTH, SMEM_BYTES>>>(x, b, out);
}

// round 9
// speedup vs baseline: 1.4380x; 1.4380x over previous
#include <cuda_runtime.h>
#include <cuda_fp16.h>
#include <math.h>
#include <stdint.h>

#define N_TOKENS 16384
#define HIDDEN   4096
#define NEXP     64
#define TOPK     8

#define BM       128          // tokens per CTA
#define TKT      128          // k per stage (two 64-k halves)
#define NT       (HIDDEN/TKT) // 32 stages
#define NTH      512          // 16 warps: 4 (M) x 4 (N), warp tile 32x16

// per-stage smem layout (bytes)
#define A_HALF   16384        // 128 rows x 64 k x 2B
#define A_TERM   32768        // 2 halves
#define A_STG    65536        // 2 terms
#define B_HALF   8192         // 64 rows x 64 k x 2B
#define B_TERM   16384
#define B_STG    32768
#define STAGE_BYTES (A_STG + B_STG)   // 98304
#define SMEM_BYTES  (1024 + 2*STAGE_BYTES)
#define CRS      72           // epilogue C row stride (floats)

#define SCALE_IN   2048.0f            // 2^11 on both x and W
#define SCALE_OUT  (1.0f/4194304.0f)  // exact 2^-22

// pre-split, pre-swizzled W (x2048, 2 fp16 terms): [stage][term][half][e][64k]
__device__ __align__(16) unsigned char g_wb[NT * B_STG];

// ---------------- helpers ----------------
__device__ __forceinline__ uint32_t smem_u32(const void* p) {
    uint32_t a;
    asm("{ .reg .u64 t; cvta.to.shared.u64 t, %1; cvt.u32.u64 %0, t; }" : "=r"(a) : "l"(p));
    return a;
}
__device__ __forceinline__ uint32_t sw128(uint32_t o) { return o ^ ((o >> 3) & 0x70); }

// pack two f32 into f16x2: lo = first arg, hi = second (first PTX src = high)
#define PACK_F16X2(res, lo, hi) \
    asm("cvt.rn.f16x2.f32 %0, %1, %2;" : "=r"(res) : "f"(hi), "f"(lo))

__device__ __forceinline__ void sts64(uint32_t a, uint32_t x, uint32_t y) {
    asm volatile("st.shared.v2.b32 [%0], {%1,%2};" :: "r"(a), "r"(x), "r"(y) : "memory");
}
__device__ __forceinline__ void cp_async16(uint32_t dst, const void* src) {
    asm volatile("cp.async.cg.shared.global [%0], [%1], 16;" :: "r"(dst), "l"(src) : "memory");
}
#define CP_COMMIT() asm volatile("cp.async.commit_group;" ::: "memory")
#define CP_WAIT0()  asm volatile("cp.async.wait_group 0;" ::: "memory")

__device__ __forceinline__ void ldsm_x4(uint32_t r[4], uint32_t addr) {
    asm volatile("ldmatrix.sync.aligned.m8n8.x4.shared.b16 {%0,%1,%2,%3}, [%4];"
        : "=r"(r[0]), "=r"(r[1]), "=r"(r[2]), "=r"(r[3]) : "r"(addr));
}
__device__ __forceinline__ void mma16816(float c[4], const uint32_t a[4],
                                         uint32_t b0, uint32_t b1) {
    asm volatile("mma.sync.aligned.m16n8k16.row.col.f32.f16.f16.f32 "
        "{%0,%1,%2,%3}, {%4,%5,%6,%7}, {%8,%9}, {%0,%1,%2,%3};"
        : "+f"(c[0]), "+f"(c[1]), "+f"(c[2]), "+f"(c[3])
        : "r"(a[0]), "r"(a[1]), "r"(a[2]), "r"(a[3]), "r"(b0), "r"(b1));
}

// x*2^11 = h0 + h1 (+ eps ~2^-22 rel). h0 roundtrip exact; r exact (Sterbenz).
__device__ __forceinline__ void splitf16(float v, float& f0, float& r) {
    f0 = __half2float(__float2half_rn(v));
    r  = v - f0;
}

// ---------------- W pre-split kernel ----------------
__global__ void wsplit_kernel(const float* __restrict__ W) {
    const int t = blockIdx.x;                 // stage (128 k)
    unsigned char* dst = g_wb + (size_t)t * B_STG;
    for (int item = threadIdx.x; item < 2048; item += blockDim.x) {
        const int e    = item >> 5;           // expert row
        const int half = (item >> 4) & 1;
        const int k    = (item & 15) * 4;     // k within half
        float4 w = *(const float4*)(W + (size_t)e * HIDDEN + t * TKT + half * 64 + k);
        float v[4] = {w.x * SCALE_IN, w.y * SCALE_IN, w.z * SCALE_IN, w.w * SCALE_IN};
        float f0[4], r[4];
#pragma unroll
        for (int i = 0; i < 4; i++) splitf16(v[i], f0[i], r[i]);
        uint32_t u0a, u0b, u1a, u1b;
        PACK_F16X2(u0a, f0[0], f0[1]); PACK_F16X2(u0b, f0[2], f0[3]);
        PACK_F16X2(u1a, r[0],  r[1]);  PACK_F16X2(u1b, r[2],  r[3]);
        const uint32_t off = half * B_HALF + sw128((uint32_t)(e * 128 + k * 2));
        *(uint2*)(dst + 0 * B_TERM + off) = make_uint2(u0a, u0b);
        *(uint2*)(dst + 1 * B_TERM + off) = make_uint2(u1a, u1b);
    }
}

// MMA over one stage (128 k), warp tile 32x16.
// h0w0 -> accM (drained per stage); h0w1, h1w0 -> accC.
__device__ __forceinline__ void mma_stage(
    uint32_t Ab, uint32_t Bb, float accM[2][2][4], float accC[2][2][4],
    uint32_t arow0, uint32_t arow1, uint32_t brow,
    uint32_t colb, uint32_t swz)
{
#pragma unroll
    for (int kk = 0; kk < 8; kk++) {
        const int half = kk >> 2, k16 = kk & 3;
        const uint32_t Ah = Ab + half * A_HALF;
        const uint32_t Bh = Bb + half * B_HALF;
        const uint32_t coff = (colb + 32u * k16) ^ swz;

        uint32_t B0[4], B1[4];
        ldsm_x4(B0, Bh + 0 * B_TERM + brow + coff);   // w0
        ldsm_x4(B1, Bh + 1 * B_TERM + brow + coff);   // w1

        uint32_t A00[4], A01[4];
        ldsm_x4(A00, Ah + 0 * A_TERM + arow0 + coff); // h0, m16 #0
        ldsm_x4(A01, Ah + 0 * A_TERM + arow1 + coff); // h0, m16 #1
        // main: h0*w0
        mma16816(accM[0][0], A00, B0[0], B0[2]);
        mma16816(accM[0][1], A00, B0[1], B0[3]);
        mma16816(accM[1][0], A01, B0[0], B0[2]);
        mma16816(accM[1][1], A01, B0[1], B0[3]);
        // corr: h0*w1
        mma16816(accC[0][0], A00, B1[0], B1[2]);
        mma16816(accC[0][1], A00, B1[1], B1[3]);
        mma16816(accC[1][0], A01, B1[0], B1[2]);
        mma16816(accC[1][1], A01, B1[1], B1[3]);

        uint32_t A10[4], A11[4];
        ldsm_x4(A10, Ah + 1 * A_TERM + arow0 + coff); // h1
        ldsm_x4(A11, Ah + 1 * A_TERM + arow1 + coff);
        // corr: h1*w0
        mma16816(accC[0][0], A10, B0[0], B0[2]);
        mma16816(accC[0][1], A10, B0[1], B0[3]);
        mma16816(accC[1][0], A11, B0[0], B0[2]);
        mma16816(accC[1][1], A11, B0[1], B0[3]);
    }
}

#define DRAIN_M()                                              \
    do {                                                       \
        _Pragma("unroll")                                      \
        for (int _i = 0; _i < 2; _i++)                         \
        _Pragma("unroll")                                      \
        for (int _j = 0; _j < 2; _j++)                         \
        _Pragma("unroll")                                      \
        for (int _q = 0; _q < 4; _q++) {                       \
            sum[_i][_j][_q] += accM[_i][_j][_q];               \
            accM[_i][_j][_q] = 0.0f;                           \
        }                                                      \
    } while (0)

// ---------------- main kernel ----------------
__global__ __launch_bounds__(NTH, 1) void router_kernel(
    const float* __restrict__ x,
    const float* __restrict__ b,
    float* __restrict__ out)
{
    extern __shared__ __align__(16) char dsmem[];
    float* biasS = (float*)dsmem;                 // [64]
    float* Cs    = (float*)(dsmem + 1024);        // epilogue [128][CRS] (stage-0 A area)
    const uint32_t TBu = smem_u32(dsmem + 1024);

    const int tid = threadIdx.x;
    const int wid = tid >> 5;
    const int lid = tid & 31;
    const int block_m = blockIdx.x * BM;

    // warp grid: 4 (M) x 4 (N), warp tile 32x16
    const int wm = (wid & 3) * 32;
    const int wn = (wid >> 2) * 16;

    // ldmatrix lane addressing
    const uint32_t lrow = (lid & 7) + ((lid >> 3) & 1) * 8;  // 0..15
    const uint32_t swz  = (lrow & 7) << 4;
    const uint32_t colb = (lid >> 4) * 16;
    const uint32_t arow0 = (wm + lrow) * 128;
    const uint32_t arow1 = arow0 + 16 * 128;
    const uint32_t brow  = (wn + lrow) * 128;

    // A conversion mapping: 32 contiguous k per thread, one row
    const int r  = tid >> 2;          // token row 0..127
    const int kq = (tid & 3) * 32;    // k base within stage (0,32,64,96)
    const int half0  = kq >> 6;       // fixed per thread
    const int klocal = kq & 63;
    const float* xrow = x + (size_t)(block_m + r) * HIDDEN + kq;

    float accM[2][2][4], accC[2][2][4], sum[2][2][4];
#pragma unroll
    for (int i = 0; i < 2; i++)
#pragma unroll
        for (int j = 0; j < 2; j++)
#pragma unroll
            for (int q = 0; q < 4; q++) {
                accM[i][j][q] = 0.0f; accC[i][j][q] = 0.0f; sum[i][j][q] = 0.0f;
            }

    const uint32_t stage[2] = {TBu, TBu + STAGE_BYTES};

    // cp.async B(0) into stage 0
#pragma unroll
    for (int j = 0; j < 4; j++) {
        const int idx = tid + j * NTH;
        cp_async16(stage[0] + A_STG + idx * 16, g_wb + (size_t)idx * 16);
    }
    CP_COMMIT();

    // prefetch A(0)
    float4 ax[8];
#pragma unroll
    for (int j = 0; j < 8; j++) ax[j] = *(const float4*)(xrow + j * 4);

    if (tid < NEXP) biasS[tid] = b[tid];

    for (int t = 0; t < NT; ++t) {
        const int p = t & 1;
        const uint32_t Abase = stage[p];

        // convert + store A(t): 2 fp16 terms, x * 2^11
#pragma unroll
        for (int j = 0; j < 8; j++) {
            float v[4] = {ax[j].x * SCALE_IN, ax[j].y * SCALE_IN,
                          ax[j].z * SCALE_IN, ax[j].w * SCALE_IN};
            float f0[4], rr[4];
#pragma unroll
            for (int i = 0; i < 4; i++) splitf16(v[i], f0[i], rr[i]);
            uint32_t u0a, u0b, u1a, u1b;
            PACK_F16X2(u0a, f0[0], f0[1]); PACK_F16X2(u0b, f0[2], f0[3]);
            PACK_F16X2(u1a, rr[0], rr[1]); PACK_F16X2(u1b, rr[2], rr[3]);
            const uint32_t off = half0 * A_HALF +
                sw128((uint32_t)(r * 128 + (klocal + j * 4) * 2));
            sts64(Abase + 0 * A_TERM + off, u0a, u0b);
            sts64(Abase + 1 * A_TERM + off, u1a, u1b);
        }

        // prefetch A(t+1)
        if (t + 1 < NT) {
            const float* xn = xrow + (size_t)(t + 1) * TKT;
#pragma unroll
            for (int j = 0; j < 8; j++) ax[j] = *(const float4*)(xn + j * 4);
        }

        // MMA over previous stage, then drain main accumulator
        if (t > 0) {
            mma_stage(stage[p ^ 1], stage[p ^ 1] + A_STG,
                      accM, accC, arow0, arow1, brow, colb, swz);
            DRAIN_M();
        }

        CP_WAIT0();          // B(t) landed
        __syncthreads();     // stage p built; stage p^1 reads done

        // cp.async B(t+1) into stage p^1
        if (t + 1 < NT) {
            const unsigned char* src = g_wb + (size_t)(t + 1) * B_STG;
#pragma unroll
            for (int j = 0; j < 4; j++) {
                const int idx = tid + j * NTH;
                cp_async16(stage[p ^ 1] + A_STG + idx * 16, src + (size_t)idx * 16);
            }
            CP_COMMIT();
        }
    }
    // final stage (t = NT-1 odd -> stage[1])
    mma_stage(stage[1], stage[1] + A_STG,
              accM, accC, arow0, arow1, brow, colb, swz);
    DRAIN_M();

    // ---- dump C = sum + corrections (stage-0 A area is dead)
#pragma unroll
    for (int im = 0; im < 2; im++)
#pragma unroll
        for (int in = 0; in < 2; in++) {
            const int r0 = wm + im * 16 + (lid >> 2);
            const int c0 = wn + in * 8 + (lid & 3) * 2;
            *(float2*)&Cs[r0 * CRS + c0] =
                make_float2(sum[im][in][0] + accC[im][in][0],
                            sum[im][in][1] + accC[im][in][1]);
            *(float2*)&Cs[(r0 + 8) * CRS + c0] =
                make_float2(sum[im][in][2] + accC[im][in][2],
                            sum[im][in][3] + accC[im][in][3]);
        }
    __syncthreads();

    if (tid < BM) {
        const int m  = tid;
        const int gm = block_m + m;
        float v[NEXP];
#pragma unroll
        for (int e = 0; e < NEXP; e++)
            v[e] = Cs[m * CRS + e] * SCALE_OUT + biasS[e];

        float* outR    = out;
        float* outWt   = out + (size_t)N_TOKENS * NEXP;
        float* outIdx  = outWt + (size_t)N_TOKENS * TOPK;
        float* outMask = outIdx + (size_t)N_TOKENS * TOPK;

        float* dst = outR + (size_t)gm * NEXP;
#pragma unroll
        for (int e = 0; e < NEXP; e += 4)
            *(float4*)(dst + e) = make_float4(v[e], v[e + 1], v[e + 2], v[e + 3]);

        // top-8, strict > (first index on ties, matching jax top_k)
        unsigned long long used = 0ull;
        float vals[TOPK]; int idxs[TOPK];
#pragma unroll
        for (int k = 0; k < TOPK; k++) {
            float best = -INFINITY; int bi = 0;
#pragma unroll
            for (int e = 0; e < NEXP; e++) {
                const bool free_e = !((used >> e) & 1ull);
                if (free_e && v[e] > best) { best = v[e]; bi = e; }
            }
            used |= 1ull << bi;
            vals[k] = best; idxs[k] = bi;
        }
        const float mx = vals[0];
        float ex[TOPK], s = 0.0f;
#pragma unroll
        for (int k = 0; k < TOPK; k++) { ex[k] = expf(vals[k] - mx); s += ex[k]; }
        const float inv = 1.0f / s;

        *(float4*)(outWt + (size_t)gm * TOPK) =
            make_float4(ex[0] * inv, ex[1] * inv, ex[2] * inv, ex[3] * inv);
        *(float4*)(outWt + (size_t)gm * TOPK + 4) =
            make_float4(ex[4] * inv, ex[5] * inv, ex[6] * inv, ex[7] * inv);
        *(float4*)(outIdx + (size_t)gm * TOPK) =
            make_float4((float)idxs[0], (float)idxs[1], (float)idxs[2], (float)idxs[3]);
        *(float4*)(outIdx + (size_t)gm * TOPK + 4) =
            make_float4((float)idxs[4], (float)idxs[5], (float)idxs[6], (float)idxs[7]);
#pragma unroll
        for (int k = 0; k < TOPK; k++)
            outMask[(size_t)(idxs[k] * TOPK + k) * N_TOKENS + gm] = 1.0f;
    }
}

extern "C" void kernel_launch(void* const* d_in, const int* in_sizes, int n_in,
                              void* d_out, int out_size)
{
    const float* x = (const float*)d_in[0];
    const float* W = (const float*)d_in[1];
    const float* b = (const float*)d_in[2];
    float* out = (float*)d_out;

    // zero the expert_mask region (rest of out fully overwritten)
    float* mask = out + (size_t)N_TOKENS * NEXP + 2 * (size_t)N_TOKENS * TOPK;
    cudaMemsetAsync(mask, 0, (size_t)NEXP * TOPK * N_TOKENS * sizeof(float), 0);

    wsplit_kernel<<<NT, 256>>>(W);

    cudaFuncSetAttribute(router_kernel,
                         cudaFuncAttributeMaxDynamicSharedMemorySize, SMEM_BYTES);
    router_kernel<<<N_TOKENS / BM, NTH, SMEM_BYTES>>>(x, b, out);
}